// round 12
// baseline (speedup 1.0000x reference)
#include <cuda_runtime.h>
#include <cuda_fp16.h>
#include <cstdint>

#define BB 4
#define NN 4096
#define CC 64
#define CEXT 72            // 64 channels + ones col (64) + 7 zero pad
#define TI 64              // i rows per block (grid = 256 -> 2 CTAs/SM)
#define TJ 128             // j per stage (2 producer halves)
#define NST (NN / TJ)      // 32 stages
#define NBUF 2
#define NTHR 512

// half-precision smem geometry: 136 halves (272 B) row stride
#define ROWB 272
#define W_BYTES (TI * ROWB)               // 17408
#define O_BYTES (CEXT * ROWB)             // 19584
#define STG_B (W_BYTES + O_BYTES)         // 36992 per stage
#define SM_W2B  (NBUF * STG_B)            // 73984
#define SM_ZSHB (SM_W2B + 16384)          // 90368
#define SMEM_BYTES (SM_ZSHB + 512)        // 90880 (~89 KB -> 2 CTAs/SM)

__device__ __half g_outT[BB * CEXT * NN];  // [b][c][n] half; row 64 = ones
__device__ float  g_sl[BB * NN];
__device__ float  g_sr[BB * NN];

__device__ __forceinline__ float ex2f(float x) {
    float r;
    asm("ex2.approx.f32 %0, %1;" : "=f"(r) : "f"(x));
    return r;
}
__device__ __forceinline__ uint32_t smem_u32(const void* p) {
    uint32_t a;
    asm("{ .reg .u64 t; cvta.to.shared.u64 t, %1; cvt.u32.u64 %0, t; }" : "=r"(a) : "l"(p));
    return a;
}
__device__ __forceinline__ void mma_f16(float d[4], const uint32_t a[4],
                                        uint32_t b0, uint32_t b1) {
    asm volatile(
        "mma.sync.aligned.m16n8k16.row.col.f32.f16.f16.f32 "
        "{%0,%1,%2,%3},{%4,%5,%6,%7},{%8,%9},{%0,%1,%2,%3};"
        : "+f"(d[0]), "+f"(d[1]), "+f"(d[2]), "+f"(d[3])
        : "r"(a[0]), "r"(a[1]), "r"(a[2]), "r"(a[3]), "r"(b0), "r"(b1));
}
#define LDSM4(r, a) \
    asm volatile("ldmatrix.sync.aligned.m8n8.x4.shared.b16 {%0,%1,%2,%3}, [%4];" \
        : "=r"((r)[0]), "=r"((r)[1]), "=r"((r)[2]), "=r"((r)[3]) : "r"(a))
#define LDSM2(r, a) \
    asm volatile("ldmatrix.sync.aligned.m8n8.x2.shared.b16 {%0,%1}, [%2];" \
        : "=r"((r)[0]), "=r"((r)[1]) : "r"(a))
#define BAR_SYNC(id)   asm volatile("bar.sync %0, 512;"   :: "r"(id) : "memory")
#define BAR_ARRIVE(id) asm volatile("bar.arrive %0, 512;" :: "r"(id) : "memory")
#define CP_ASYNC16(dst, src) \
    asm volatile("cp.async.cg.shared.global [%0], [%1], 16;" :: "r"(dst), "l"(src) : "memory")
#define CP_COMMIT() asm volatile("cp.async.commit_group;" ::: "memory")
#define CP_WAIT0()  asm volatile("cp.async.wait_group 0;" ::: "memory")

// ---------------------------------------------------------------------------
// prep (unchanged, proven): out = X@W1; g_outT half transposed (+ones/zeros)
// ---------------------------------------------------------------------------
#define PREP_SMEM_FLOATS (4096 + 128 * 65 + 128)
__global__ __launch_bounds__(256) void prep_kernel(
    const float* __restrict__ X, const float* __restrict__ W1,
    const float* __restrict__ alpha)
{
    extern __shared__ float psm[];
    float* W1s = psm;
    float* Xs  = psm + 4096;
    float* al  = psm + 4096 + 128 * 65;
    float* ar  = al + 64;

    const int tid = threadIdx.x;
    const int gr0 = blockIdx.x * 128;
    const int b0  = gr0 >> 12;
    const int n0  = gr0 & (NN - 1);

    for (int i = tid; i < 1024; i += 256)
        reinterpret_cast<float4*>(W1s)[i] = reinterpret_cast<const float4*>(W1)[i];
    for (int i = tid; i < 2048; i += 256) {
        int r = i >> 4, q = i & 15;
        float4 v = reinterpret_cast<const float4*>(X + (size_t)(gr0 + r) * CC)[q];
        Xs[r * 65 + 4 * q + 0] = v.x; Xs[r * 65 + 4 * q + 1] = v.y;
        Xs[r * 65 + 4 * q + 2] = v.z; Xs[r * 65 + 4 * q + 3] = v.w;
    }
    if (tid < 64)       al[tid]      = alpha[tid];
    else if (tid < 128) ar[tid - 64] = alpha[tid];
    __syncthreads();

    const int r  = tid >> 2;
    const int c0 = tid & 3;

    float acc0[16], acc1[16];
#pragma unroll
    for (int q = 0; q < 16; q++) { acc0[q] = 0.f; acc1[q] = 0.f; }
    const float4* W1v = reinterpret_cast<const float4*>(W1s);
#pragma unroll 4
    for (int k = 0; k < 64; k++) {
        float x0 = Xs[r * 65 + k];
        float x1 = Xs[(r + 64) * 65 + k];
#pragma unroll
        for (int h = 0; h < 4; h++) {
            float4 wv = W1v[k * 16 + 4 * c0 + h];
            acc0[4 * h + 0] += x0 * wv.x; acc1[4 * h + 0] += x1 * wv.x;
            acc0[4 * h + 1] += x0 * wv.y; acc1[4 * h + 1] += x1 * wv.y;
            acc0[4 * h + 2] += x0 * wv.z; acc1[4 * h + 2] += x1 * wv.z;
            acc0[4 * h + 3] += x0 * wv.w; acc1[4 * h + 3] += x1 * wv.w;
        }
    }

    float vl0 = 0.f, vr0 = 0.f, vl1 = 0.f, vr1 = 0.f;
#pragma unroll
    for (int q = 0; q < 16; q++) {
        float a_ = al[16 * c0 + q], r_ = ar[16 * c0 + q];
        vl0 += acc0[q] * a_; vr0 += acc0[q] * r_;
        vl1 += acc1[q] * a_; vr1 += acc1[q] * r_;
    }
#pragma unroll
    for (int o = 1; o <= 2; o <<= 1) {
        vl0 += __shfl_xor_sync(0xffffffffu, vl0, o);
        vr0 += __shfl_xor_sync(0xffffffffu, vr0, o);
        vl1 += __shfl_xor_sync(0xffffffffu, vl1, o);
        vr1 += __shfl_xor_sync(0xffffffffu, vr1, o);
    }
    if (c0 == 0) {
        g_sl[gr0 + r] = vl0;       g_sr[gr0 + r] = vr0;
        g_sl[gr0 + r + 64] = vl1;  g_sr[gr0 + r + 64] = vr1;
    }

    __half* oT = g_outT;
    size_t base0 = (size_t)b0 * CEXT * NN + (n0 + r);
#pragma unroll
    for (int q = 0; q < 16; q++) {
        size_t coff = (size_t)(16 * c0 + q) * NN;
        oT[base0 + coff]      = __float2half_rn(acc0[q]);
        oT[base0 + 64 + coff] = __float2half_rn(acc1[q]);
    }

#pragma unroll
    for (int p = 0; p < 4; p++) {
        int it = tid + 256 * p;
        int rr = 64 + (it >> 7);
        int nn = n0 + (it & 127);
        g_outT[(size_t)b0 * CEXT * NN + (size_t)rr * NN + nn] =
            __float2half_rn((rr == 64) ? 1.0f : 0.0f);
    }
}

// ---------------------------------------------------------------------------
// attn: fp16 mma + ldmatrix, TI=64 / TJ=128, 2 CTAs per SM.
// 512 threads: warps 0..7 consumers (4 wm x 16 rows, 2 wn), 8..15 producers.
// barrier ids: full = 1+buf (1..2), empty = 3+buf (3..4)
// ---------------------------------------------------------------------------
template<int NT>
__device__ __forceinline__ void consume_tile(
    uint32_t wA, uint32_t wB, uint32_t wB2, float acc[5][4])
{
#pragma unroll
    for (int ks = 0; ks < 8; ks++) {
        const uint32_t ko = (uint32_t)ks * 32;
        uint32_t a0[4], bb[10];
        LDSM4(a0, wA + ko);
        LDSM4(bb + 0, wB + ko);             // nt 0,1
        LDSM4(bb + 4, wB + 16 * ROWB + ko); // nt 2,3
        if (NT == 5) LDSM2(bb + 8, wB2 + ko);
#pragma unroll
        for (int nt = 0; nt < NT; nt++)
            mma_f16(acc[nt], a0, bb[2 * nt], bb[2 * nt + 1]);
    }
}

__global__ void __launch_bounds__(NTHR, 2) attn_kernel(
    const float* __restrict__ A_, const float* __restrict__ W2,
    float* __restrict__ out)
{
    extern __shared__ char sm[];
    const uint32_t smb = smem_u32(sm);
    float* W2s = reinterpret_cast<float*>(sm + SM_W2B);
    float* Zsh = reinterpret_cast<float*>(sm + SM_ZSHB);

    const int b      = blockIdx.y;
    const int i_base = blockIdx.x * TI;
    const int tid    = threadIdx.x;

    for (int i = tid; i < 1024; i += NTHR)
        reinterpret_cast<float4*>(W2s)[i] = reinterpret_cast<const float4*>(W2)[i];
    __syncthreads();

    if (tid < 256) {
        // ---------------- consumers (8 warps) ----------------
        const int lane = tid & 31, wid = tid >> 5;
        const int wm = wid & 3, wn = wid >> 2;
        const int r = lane >> 2, cq = lane & 3;
        const int moff = wm * 16, noff = wn * 40;

        const uint32_t aoff = (uint32_t)((lane & 15) * ROWB + (lane >> 4) * 16);
        const uint32_t boff = (uint32_t)((((lane & 7) + ((lane >> 4) & 1) * 8)) * ROWB
                                         + ((lane >> 3) & 1) * 16);
        const uint32_t boff2 = (uint32_t)((lane & 7) * ROWB + ((lane >> 3) & 1) * 16);

        const uint32_t wA  = smb + (uint32_t)moff * ROWB + aoff;
        const uint32_t wB  = smb + W_BYTES + (uint32_t)noff * ROWB + boff;
        const uint32_t wB2 = smb + W_BYTES + (uint32_t)(noff + 32) * ROWB + boff2;

        float acc[5][4];
#pragma unroll
        for (int nt = 0; nt < 5; nt++)
#pragma unroll
            for (int e = 0; e < 4; e++) acc[nt][e] = 0.f;

        for (int s = 0; s < NST; s++) {
            const int buf = s & 1;
            BAR_SYNC(1 + buf);
            const uint32_t bo = (uint32_t)buf * STG_B;
            if (wn == 0) consume_tile<5>(wA + bo, wB + bo, wB2 + bo, acc);
            else         consume_tile<4>(wA + bo, wB + bo, wB2 + bo, acc);
            BAR_ARRIVE(3 + buf);
        }

        // Z = ones column (col 64): wn==1, nt==3, frag col 0 (cq==0)
        if (wn == 1 && cq == 0) {
            Zsh[moff + r]     = acc[3][0];
            Zsh[moff + 8 + r] = acc[3][2];
        }
        __syncthreads();   // (A)

        float* aggS = reinterpret_cast<float*>(sm);   // 64 x 68 fp32 (stride 68)
        const int ntmax = (wn == 0) ? 5 : 3;
        {
            int rr = moff + r;
            float z0 = 1.0f / Zsh[rr];
            float z1 = 1.0f / Zsh[rr + 8];
#pragma unroll
            for (int nt = 0; nt < 5; nt++) {
                if (nt >= ntmax) break;
                int col = noff + nt * 8 + 2 * cq;
                aggS[rr * 68 + col]           = acc[nt][0] * z0;
                aggS[rr * 68 + col + 1]       = acc[nt][1] * z0;
                aggS[(rr + 8) * 68 + col]     = acc[nt][2] * z1;
                aggS[(rr + 8) * 68 + col + 1] = acc[nt][3] * z1;
            }
        }
    } else {
        // ---------------- producers (8 warps, 256 threads) ----------------
        const int ptid = tid - 256;
        const int jj8  = ptid & 7;          // 8-col group within a 64-wide half
        const int rgrp = ptid >> 3;         // rows rgrp + 32k, k<2

        const float*  Abase = A_ + (size_t)(i_base + rgrp) * NN + 8 * jj8;
        const __half* oTb   = g_outT + (size_t)b * CEXT * NN;
        const float*  srb   = g_sr + b * NN + 8 * jj8;

        float cl[2];
        unsigned fl[2];
#pragma unroll
        for (int k = 0; k < 2; k++) {
            float s_ = g_sl[b * NN + i_base + rgrp + 32 * k];
            fl[k] = (s_ > 0.f);
            cl[k] = fabsf(s_) * 1.44269504f;
        }

        // o-tile cp.async: 72 rows x 16 chunks (16B) = 1152
        uint32_t odst[5];
        int      osrc[5];
#pragma unroll
        for (int p = 0; p < 5; p++) {
            int it = ptid + 256 * p;
            int rr = it >> 4, q = it & 15;
            odst[p] = (uint32_t)(rr * ROWB + 16 * q);
            osrc[p] = rr * NN + 8 * q;
        }
        const bool ov4 = (ptid < 128);

        // diagonal stage/half for this block
        const int dstage = i_base / TJ;
        const int dhalf  = (i_base >> 6) & 1;

        float4 a4[2][2], sr4[2][2];

        auto load_half = [&](int jb, int h) {
            const int off = jb + 64 * h;
#pragma unroll
            for (int k = 0; k < 2; k++) {
                a4[k][0] = *reinterpret_cast<const float4*>(Abase + (size_t)(32 * k) * NN + off);
                a4[k][1] = *reinterpret_cast<const float4*>(Abase + (size_t)(32 * k) * NN + off + 4);
            }
        };
        auto load_sr = [&](int jb) {
            sr4[0][0] = *reinterpret_cast<const float4*>(srb + jb);
            sr4[0][1] = *reinterpret_cast<const float4*>(srb + jb + 4);
            sr4[1][0] = *reinterpret_cast<const float4*>(srb + jb + 64);
            sr4[1][1] = *reinterpret_cast<const float4*>(srb + jb + 68);
        };

        auto compute_half = [&](int h, int s, uint4* wu) {
            if (s == dstage && h == dhalf) {
#pragma unroll
                for (int k = 0; k < 2; k++) {
                    int colh = rgrp + 32 * k;   // diag col within this half
                    if ((colh >> 3) == jj8)
                        reinterpret_cast<float*>(&a4[k][0])[colh & 7] = 1.0f;
                }
            }
            float lp[8], lm[8];
            const float* srv = reinterpret_cast<const float*>(&sr4[h][0]);
#pragma unroll
            for (int e = 0; e < 8; e++) {
                lp[e] = fmaxf(srv[e], 0.01f * srv[e]);
                lm[e] = fmaxf(-srv[e], -0.01f * srv[e]);
            }
#pragma unroll
            for (int k = 0; k < 2; k++) {
                const float* av = reinterpret_cast<const float*>(&a4[k][0]);
                const int row = rgrp + 32 * k;
                uint32_t hh[4];
#pragma unroll
                for (int e2 = 0; e2 < 4; e2++) {
                    float t0 = cl[k] * (fl[k] ? lp[2 * e2]     : lm[2 * e2]);
                    float t1 = cl[k] * (fl[k] ? lp[2 * e2 + 1] : lm[2 * e2 + 1]);
                    __half2 hv = __floats2half2_rn(ex2f(t0) * av[2 * e2],
                                                   ex2f(t1) * av[2 * e2 + 1]);
                    hh[e2] = *reinterpret_cast<uint32_t*>(&hv);
                }
                wu[row * (ROWB / 16) + 8 * h + jj8] =
                    make_uint4(hh[0], hh[1], hh[2], hh[3]);
            }
        };

        load_half(0, 0);
        load_sr(0);

        for (int s = 0; s < NST; s++) {
            const int buf = s & 1;
            if (s >= NBUF) BAR_SYNC(3 + buf);
            const uint32_t bo = (uint32_t)buf * STG_B;
            const int jb = s * TJ;

            const uint32_t obase = smb + bo + W_BYTES;
#pragma unroll
            for (int p = 0; p < 4; p++)
                CP_ASYNC16(obase + odst[p], oTb + osrc[p] + jb);
            if (ov4) CP_ASYNC16(obase + odst[4], oTb + osrc[4] + jb);
            CP_COMMIT();

            uint4* wu = reinterpret_cast<uint4*>(sm + bo);
            compute_half(0, s, wu);
            load_half(jb, 1);
            compute_half(1, s, wu);

            CP_WAIT0();
            BAR_ARRIVE(1 + buf);
            if (s + 1 < NST) {
                load_half((s + 1) * TJ, 0);
                load_sr((s + 1) * TJ);
            }
        }
        __syncthreads();   // (A)
    }

    __syncthreads();       // (B) aggS ready

    // epilogue: out = aggS(64x64) @ W2(64x64), threads 0..255
    if (tid < 256) {
        const float* aggS = reinterpret_cast<const float*>(sm);
        const int r0 = tid >> 2;
        const int c0 = tid & 3;
        float res[16];
#pragma unroll
        for (int q = 0; q < 16; q++) res[q] = 0.f;
#pragma unroll 8
        for (int k = 0; k < 64; k++) {
            float a0 = aggS[r0 * 68 + k];
#pragma unroll
            for (int q = 0; q < 16; q++)
                res[q] += a0 * W2s[k * 64 + c0 + 4 * q];
        }
        float* ob = out + (size_t)(b * NN + i_base + r0) * CC;
#pragma unroll
        for (int q = 0; q < 16; q++)
            ob[c0 + 4 * q] = res[q];
    }
}

// ---------------------------------------------------------------------------
extern "C" void kernel_launch(void* const* d_in, const int* in_sizes, int n_in,
                              void* d_out, int out_size)
{
    (void)in_sizes; (void)n_in; (void)out_size;
    const float* X  = (const float*)d_in[0];
    const float* A_ = (const float*)d_in[1];
    const float* W1 = (const float*)d_in[2];
    const float* W2 = (const float*)d_in[3];
    const float* al = (const float*)d_in[4];
    float* out = (float*)d_out;

    cudaFuncSetAttribute(attn_kernel, cudaFuncAttributeMaxDynamicSharedMemorySize,
                         SMEM_BYTES);
    cudaFuncSetAttribute(prep_kernel, cudaFuncAttributeMaxDynamicSharedMemorySize,
                         PREP_SMEM_FLOATS * 4);

    prep_kernel<<<BB * NN / 128, 256, PREP_SMEM_FLOATS * 4>>>(X, W1, al);

    dim3 grid(NN / TI, BB);
    attn_kernel<<<grid, NTHR, SMEM_BYTES>>>(A_, W2, out);
}

// round 13
// speedup vs baseline: 1.0730x; 1.0730x over previous
#include <cuda_runtime.h>
#include <cuda_fp16.h>
#include <cstdint>

#define BB 4
#define NN 4096
#define CC 64
#define OROWS 64           // o-tile rows (no ones/pad columns)
#define TI 128             // i rows per block
#define TJ 128             // j per stage (2 producer halves)
#define NST (NN / TJ)      // 32 stages
#define NBUF 2
#define NTHR 512

// half-precision smem geometry: 136 halves (272 B) row stride
#define ROWB 272
#define W_BYTES (TI * ROWB)               // 34816
#define O_BYTES (OROWS * ROWB)            // 17408
#define STG_B (W_BYTES + O_BYTES)         // 52224 per stage
#define SM_W2B  (NBUF * STG_B)            // 104448
#define SM_ZSHB (SM_W2B + 16384)          // 120832
#define SMEM_BYTES (SM_ZSHB + 512)        // ~118.5 KB

__device__ __half g_outT[BB * OROWS * NN]; // [b][c][n] half
__device__ float  g_sl[BB * NN];
__device__ float  g_sr[BB * NN];

__device__ __forceinline__ float ex2f(float x) {
    float r;
    asm("ex2.approx.f32 %0, %1;" : "=f"(r) : "f"(x));
    return r;
}
__device__ __forceinline__ uint32_t smem_u32(const void* p) {
    uint32_t a;
    asm("{ .reg .u64 t; cvta.to.shared.u64 t, %1; cvt.u32.u64 %0, t; }" : "=r"(a) : "l"(p));
    return a;
}
__device__ __forceinline__ void mma_f16(float d[4], const uint32_t a[4],
                                        uint32_t b0, uint32_t b1) {
    asm volatile(
        "mma.sync.aligned.m16n8k16.row.col.f32.f16.f16.f32 "
        "{%0,%1,%2,%3},{%4,%5,%6,%7},{%8,%9},{%0,%1,%2,%3};"
        : "+f"(d[0]), "+f"(d[1]), "+f"(d[2]), "+f"(d[3])
        : "r"(a[0]), "r"(a[1]), "r"(a[2]), "r"(a[3]), "r"(b0), "r"(b1));
}
#define LDSM4(r, a) \
    asm volatile("ldmatrix.sync.aligned.m8n8.x4.shared.b16 {%0,%1,%2,%3}, [%4];" \
        : "=r"((r)[0]), "=r"((r)[1]), "=r"((r)[2]), "=r"((r)[3]) : "r"(a))
#define BAR_SYNC(id)   asm volatile("bar.sync %0, 512;"   :: "r"(id) : "memory")
#define BAR_ARRIVE(id) asm volatile("bar.arrive %0, 512;" :: "r"(id) : "memory")
#define CP_ASYNC16(dst, src) \
    asm volatile("cp.async.cg.shared.global [%0], [%1], 16;" :: "r"(dst), "l"(src) : "memory")
#define CP_COMMIT() asm volatile("cp.async.commit_group;" ::: "memory")
#define CP_WAIT0()  asm volatile("cp.async.wait_group 0;" ::: "memory")

// ---------------------------------------------------------------------------
// prep: out = X@W1; g_outT = half(out) transposed; sl, sr
// ---------------------------------------------------------------------------
#define PREP_SMEM_FLOATS (4096 + 128 * 65 + 128)
__global__ __launch_bounds__(256) void prep_kernel(
    const float* __restrict__ X, const float* __restrict__ W1,
    const float* __restrict__ alpha)
{
    extern __shared__ float psm[];
    float* W1s = psm;
    float* Xs  = psm + 4096;
    float* al  = psm + 4096 + 128 * 65;
    float* ar  = al + 64;

    const int tid = threadIdx.x;
    const int gr0 = blockIdx.x * 128;
    const int b0  = gr0 >> 12;
    const int n0  = gr0 & (NN - 1);

    for (int i = tid; i < 1024; i += 256)
        reinterpret_cast<float4*>(W1s)[i] = reinterpret_cast<const float4*>(W1)[i];
    for (int i = tid; i < 2048; i += 256) {
        int r = i >> 4, q = i & 15;
        float4 v = reinterpret_cast<const float4*>(X + (size_t)(gr0 + r) * CC)[q];
        Xs[r * 65 + 4 * q + 0] = v.x; Xs[r * 65 + 4 * q + 1] = v.y;
        Xs[r * 65 + 4 * q + 2] = v.z; Xs[r * 65 + 4 * q + 3] = v.w;
    }
    if (tid < 64)       al[tid]      = alpha[tid];
    else if (tid < 128) ar[tid - 64] = alpha[tid];
    __syncthreads();

    const int r  = tid >> 2;
    const int c0 = tid & 3;

    float acc0[16], acc1[16];
#pragma unroll
    for (int q = 0; q < 16; q++) { acc0[q] = 0.f; acc1[q] = 0.f; }
    const float4* W1v = reinterpret_cast<const float4*>(W1s);
#pragma unroll 4
    for (int k = 0; k < 64; k++) {
        float x0 = Xs[r * 65 + k];
        float x1 = Xs[(r + 64) * 65 + k];
#pragma unroll
        for (int h = 0; h < 4; h++) {
            float4 wv = W1v[k * 16 + 4 * c0 + h];
            acc0[4 * h + 0] += x0 * wv.x; acc1[4 * h + 0] += x1 * wv.x;
            acc0[4 * h + 1] += x0 * wv.y; acc1[4 * h + 1] += x1 * wv.y;
            acc0[4 * h + 2] += x0 * wv.z; acc1[4 * h + 2] += x1 * wv.z;
            acc0[4 * h + 3] += x0 * wv.w; acc1[4 * h + 3] += x1 * wv.w;
        }
    }

    float vl0 = 0.f, vr0 = 0.f, vl1 = 0.f, vr1 = 0.f;
#pragma unroll
    for (int q = 0; q < 16; q++) {
        float a_ = al[16 * c0 + q], r_ = ar[16 * c0 + q];
        vl0 += acc0[q] * a_; vr0 += acc0[q] * r_;
        vl1 += acc1[q] * a_; vr1 += acc1[q] * r_;
    }
#pragma unroll
    for (int o = 1; o <= 2; o <<= 1) {
        vl0 += __shfl_xor_sync(0xffffffffu, vl0, o);
        vr0 += __shfl_xor_sync(0xffffffffu, vr0, o);
        vl1 += __shfl_xor_sync(0xffffffffu, vl1, o);
        vr1 += __shfl_xor_sync(0xffffffffu, vr1, o);
    }
    if (c0 == 0) {
        g_sl[gr0 + r] = vl0;       g_sr[gr0 + r] = vr0;
        g_sl[gr0 + r + 64] = vl1;  g_sr[gr0 + r + 64] = vr1;
    }

    __half* oT = g_outT;
    size_t base0 = (size_t)b0 * OROWS * NN + (n0 + r);
#pragma unroll
    for (int q = 0; q < 16; q++) {
        size_t coff = (size_t)(16 * c0 + q) * NN;
        oT[base0 + coff]      = __float2half_rn(acc0[q]);
        oT[base0 + 64 + coff] = __float2half_rn(acc1[q]);
    }
}

// ---------------------------------------------------------------------------
// attn: fp16 mma + ldmatrix, TI=TJ=128, N=64 (Z computed by producers in fp32).
// 512 threads: warps 0..7 consumers (4 wm x 2 wn, uniform nt=4),
//              warps 8..15 producers (w tiles + o cp.async + Z accumulation).
// barrier ids: full = 1+buf (1..2), empty = 3+buf (3..4)
// ---------------------------------------------------------------------------
__device__ __forceinline__ void consume_tile(
    uint32_t wA, uint32_t wB, float acc[2][4][4])
{
#pragma unroll
    for (int ks = 0; ks < 8; ks++) {
        const uint32_t ko = (uint32_t)ks * 32;
        uint32_t a0[4], a1[4], bb[8];
        LDSM4(a0, wA + ko);
        LDSM4(a1, wA + 16 * ROWB + ko);     // +16 rows
        LDSM4(bb + 0, wB + ko);             // nt 0,1
        LDSM4(bb + 4, wB + 16 * ROWB + ko); // nt 2,3
#pragma unroll
        for (int nt = 0; nt < 4; nt++) {
            mma_f16(acc[0][nt], a0, bb[2 * nt], bb[2 * nt + 1]);
            mma_f16(acc[1][nt], a1, bb[2 * nt], bb[2 * nt + 1]);
        }
    }
}

__global__ void __launch_bounds__(NTHR, 1) attn_kernel(
    const float* __restrict__ A_, const float* __restrict__ W2,
    float* __restrict__ out)
{
    extern __shared__ char sm[];
    const uint32_t smb = smem_u32(sm);
    float* W2s = reinterpret_cast<float*>(sm + SM_W2B);
    float* Zsh = reinterpret_cast<float*>(sm + SM_ZSHB);

    const int b      = blockIdx.y;
    const int i_base = blockIdx.x * TI;
    const int tid    = threadIdx.x;

    for (int i = tid; i < 1024; i += NTHR)
        reinterpret_cast<float4*>(W2s)[i] = reinterpret_cast<const float4*>(W2)[i];
    __syncthreads();

    if (tid < 256) {
        // ---------------- consumers (8 warps) ----------------
        const int lane = tid & 31, wid = tid >> 5;
        const int wm = wid & 3, wn = wid >> 2;
        const int r = lane >> 2, cq = lane & 3;
        const int moff = wm * 32, noff = wn * 32;

        const uint32_t aoff = (uint32_t)((lane & 15) * ROWB + (lane >> 4) * 16);
        const uint32_t boff = (uint32_t)((((lane & 7) + ((lane >> 4) & 1) * 8)) * ROWB
                                         + ((lane >> 3) & 1) * 16);

        const uint32_t wA = smb + (uint32_t)moff * ROWB + aoff;
        const uint32_t wB = smb + W_BYTES + (uint32_t)noff * ROWB + boff;

        float acc[2][4][4];
#pragma unroll
        for (int mt = 0; mt < 2; mt++)
#pragma unroll
            for (int nt = 0; nt < 4; nt++)
#pragma unroll
                for (int e = 0; e < 4; e++) acc[mt][nt][e] = 0.f;

        for (int s = 0; s < NST; s++) {
            const int buf = s & 1;
            BAR_SYNC(1 + buf);
            const uint32_t bo = (uint32_t)buf * STG_B;
            consume_tile(wA + bo, wB + bo, acc);
            BAR_ARRIVE(3 + buf);
        }

        __syncthreads();   // (A) -- producers have written Zsh

        float* aggS = reinterpret_cast<float*>(sm);   // 128 x 68 fp32 (stride 68)
#pragma unroll
        for (int mt = 0; mt < 2; mt++) {
            int rr = moff + mt * 16 + r;
            float z0 = 1.0f / Zsh[rr];
            float z1 = 1.0f / Zsh[rr + 8];
#pragma unroll
            for (int nt = 0; nt < 4; nt++) {
                int col = noff + nt * 8 + 2 * cq;
                aggS[rr * 68 + col]           = acc[mt][nt][0] * z0;
                aggS[rr * 68 + col + 1]       = acc[mt][nt][1] * z0;
                aggS[(rr + 8) * 68 + col]     = acc[mt][nt][2] * z1;
                aggS[(rr + 8) * 68 + col + 1] = acc[mt][nt][3] * z1;
            }
        }
    } else {
        // ---------------- producers (8 warps, 256 threads) ----------------
        const int ptid = tid - 256;
        const int jj8  = ptid & 7;          // 8-col group within a 64-wide half
        const int rgrp = ptid >> 3;         // rows rgrp + 32k, k<4

        const float*  Abase = A_ + (size_t)(i_base + rgrp) * NN + 8 * jj8;
        const __half* oTb   = g_outT + (size_t)b * OROWS * NN;
        const float*  srb   = g_sr + b * NN + 8 * jj8;

        float cl[4];
        unsigned fl[4];
#pragma unroll
        for (int k = 0; k < 4; k++) {
            float s_ = g_sl[b * NN + i_base + rgrp + 32 * k];
            fl[k] = (s_ > 0.f);
            cl[k] = fabsf(s_) * 1.44269504f;
        }

        // o-tile cp.async: 64 rows x 16 chunks (16B) = 1024 -> 4 per thread
        uint32_t odst[4];
        int      osrc[4];
#pragma unroll
        for (int p = 0; p < 4; p++) {
            int it = ptid + 256 * p;
            int rr = it >> 4, q = it & 15;
            odst[p] = (uint32_t)(rr * ROWB + 16 * q);
            osrc[p] = rr * NN + 8 * q;
        }

        const int dstage = i_base / TJ;     // diagonal stage for this block
        float zacc[4] = {0.f, 0.f, 0.f, 0.f};

        float4 a4[4][2], sr4[2][2];

        auto load_half = [&](int jb, int h) {
            const int off = jb + 64 * h;
#pragma unroll
            for (int k = 0; k < 4; k++) {
                a4[k][0] = *reinterpret_cast<const float4*>(Abase + (size_t)(32 * k) * NN + off);
                a4[k][1] = *reinterpret_cast<const float4*>(Abase + (size_t)(32 * k) * NN + off + 4);
            }
        };
        auto load_sr = [&](int jb) {
            sr4[0][0] = *reinterpret_cast<const float4*>(srb + jb);
            sr4[0][1] = *reinterpret_cast<const float4*>(srb + jb + 4);
            sr4[1][0] = *reinterpret_cast<const float4*>(srb + jb + 64);
            sr4[1][1] = *reinterpret_cast<const float4*>(srb + jb + 68);
        };

        auto compute_half = [&](int h, int s, uint4* wu) {
            // diagonal fixup: rows k = 2h, 2h+1 have their diag col in half h
            if (s == dstage) {
#pragma unroll
                for (int kk = 0; kk < 2; kk++) {
                    int k = 2 * h + kk;
                    int colh = rgrp + 32 * kk;   // col within this half
                    if ((colh >> 3) == jj8)
                        reinterpret_cast<float*>(&a4[k][0])[colh & 7] = 1.0f;
                }
            }
            float lp[8], lm[8];
            const float* srv = reinterpret_cast<const float*>(&sr4[h][0]);
#pragma unroll
            for (int e = 0; e < 8; e++) {
                lp[e] = fmaxf(srv[e], 0.01f * srv[e]);
                lm[e] = fmaxf(-srv[e], -0.01f * srv[e]);
            }
#pragma unroll
            for (int k = 0; k < 4; k++) {
                const float* av = reinterpret_cast<const float*>(&a4[k][0]);
                const int row = rgrp + 32 * k;
                uint32_t hh[4];
#pragma unroll
                for (int e2 = 0; e2 < 4; e2++) {
                    float t0 = cl[k] * (fl[k] ? lp[2 * e2]     : lm[2 * e2]);
                    float t1 = cl[k] * (fl[k] ? lp[2 * e2 + 1] : lm[2 * e2 + 1]);
                    float f0 = ex2f(t0) * av[2 * e2];
                    float f1 = ex2f(t1) * av[2 * e2 + 1];
                    zacc[k] += f0 + f1;
                    __half2 hv = __floats2half2_rn(f0, f1);
                    hh[e2] = *reinterpret_cast<uint32_t*>(&hv);
                }
                wu[row * (ROWB / 16) + 8 * h + jj8] =
                    make_uint4(hh[0], hh[1], hh[2], hh[3]);
            }
        };

        load_half(0, 0);
        load_sr(0);

        for (int s = 0; s < NST; s++) {
            const int buf = s & 1;
            if (s >= NBUF) BAR_SYNC(3 + buf);
            const uint32_t bo = (uint32_t)buf * STG_B;
            const int jb = s * TJ;

            const uint32_t obase = smb + bo + W_BYTES;
#pragma unroll
            for (int p = 0; p < 4; p++)
                CP_ASYNC16(obase + odst[p], oTb + osrc[p] + jb);
            CP_COMMIT();

            uint4* wu = reinterpret_cast<uint4*>(sm + bo);
            compute_half(0, s, wu);
            load_half(jb, 1);              // reload a4 with half 1
            compute_half(1, s, wu);

            CP_WAIT0();
            BAR_ARRIVE(1 + buf);
            if (s + 1 < NST) {
                load_half((s + 1) * TJ, 0);
                load_sr((s + 1) * TJ);
            }
        }

        // Z reduction: sum across the 8 jj8-threads (consecutive lanes)
#pragma unroll
        for (int k = 0; k < 4; k++) {
            zacc[k] += __shfl_xor_sync(0xffffffffu, zacc[k], 1);
            zacc[k] += __shfl_xor_sync(0xffffffffu, zacc[k], 2);
            zacc[k] += __shfl_xor_sync(0xffffffffu, zacc[k], 4);
        }
        if (jj8 == 0) {
#pragma unroll
            for (int k = 0; k < 4; k++)
                Zsh[rgrp + 32 * k] = zacc[k];
        }
        __syncthreads();   // (A)
    }

    __syncthreads();       // (B) aggS ready

    // epilogue: out = aggS(128x64) @ W2(64x64), all 512 threads
    const float* aggS = reinterpret_cast<const float*>(sm);
    const int r0 = tid >> 2;
    const int c0 = tid & 3;
    float res[16];
#pragma unroll
    for (int q = 0; q < 16; q++) res[q] = 0.f;
#pragma unroll 8
    for (int k = 0; k < 64; k++) {
        float a0 = aggS[r0 * 68 + k];
#pragma unroll
        for (int q = 0; q < 16; q++)
            res[q] += a0 * W2s[k * 64 + c0 + 4 * q];
    }
    float* ob = out + (size_t)(b * NN + i_base + r0) * CC;
#pragma unroll
    for (int q = 0; q < 16; q++)
        ob[c0 + 4 * q] = res[q];
}

// ---------------------------------------------------------------------------
extern "C" void kernel_launch(void* const* d_in, const int* in_sizes, int n_in,
                              void* d_out, int out_size)
{
    (void)in_sizes; (void)n_in; (void)out_size;
    const float* X  = (const float*)d_in[0];
    const float* A_ = (const float*)d_in[1];
    const float* W1 = (const float*)d_in[2];
    const float* W2 = (const float*)d_in[3];
    const float* al = (const float*)d_in[4];
    float* out = (float*)d_out;

    cudaFuncSetAttribute(attn_kernel, cudaFuncAttributeMaxDynamicSharedMemorySize,
                         SMEM_BYTES);
    cudaFuncSetAttribute(prep_kernel, cudaFuncAttributeMaxDynamicSharedMemorySize,
                         PREP_SMEM_FLOATS * 4);

    prep_kernel<<<BB * NN / 128, 256, PREP_SMEM_FLOATS * 4>>>(X, W1, al);

    dim3 grid(NN / TI, BB);
    attn_kernel<<<grid, NTHR, SMEM_BYTES>>>(A_, W2, out);
}